// round 4
// baseline (speedup 1.0000x reference)
#include <cuda_runtime.h>
#include <stdint.h>

// Problem constants
#define BB 32
#define NN 1024
#define DD 768
#define D4 (DD/4)          // 192 float4 per row
#define KMASK 768          // masked tokens per row
#define NUNM  256          // unmasked tokens per row

#define TOK_PER_BLK 16     // tokens per scatter block
#define SCAT_PER_BATCH (NN / TOK_PER_BLK)       // 64
#define N_SCAT_BLKS (BB * SCAT_PER_BATCH)       // 2048
#define N_BLKS (BB + N_SCAT_BLKS)               // 2080

// Output layout (float32 concat of the 5 reference outputs, flattened in order)
#define OFF_WITHMASK 0ull
#define OFF_UNMP   ((unsigned long long)BB*NN*DD)                       // 25165824
#define OFF_BOOL   (OFF_UNMP + (unsigned long long)BB*NUNM*DD)          // 31457280
#define OFF_MIDX   (OFF_BOOL + (unsigned long long)BB*NN*DD)            // 56623104
#define OFF_UIDX   (OFF_MIDX + (unsigned long long)BB*KMASK)            // 56647680

// Scratch
__device__ int g_info[BB * NN];   // -1 => masked; else rank among unmasked
__device__ int g_flag[BB];        // batch b sort complete (zero-init; restored)
__device__ int g_done[BB];        // consumer count per batch (zero-init; restored)

__global__ __launch_bounds__(1024, 1)
void mask_fused_kernel(const float* __restrict__ patch,
                       const float* __restrict__ noise,
                       const float* __restrict__ mask_emb,
                       float* __restrict__ out)
{
    __shared__ unsigned long long sbuf[2][NN];   // sort exchange (16 KB)
    __shared__ int warp_sums[32];
    __shared__ float4 s_me[D4];                  // mask_emb (3 KB)
    __shared__ int s_info[TOK_PER_BLK];

    const int t = threadIdx.x;

    if (blockIdx.x < BB) {
        // ===================== PRODUCER: sort batch b =====================
        const int b = blockIdx.x;

        float v = noise[b * NN + t];
        unsigned long long key =
            ((unsigned long long)__float_as_uint(v) << 32) | (unsigned)t;

        // Hybrid register/shuffle bitonic (stable argsort; verified R3)
        int p = 0;
        #pragma unroll 1
        for (int k = 2; k <= NN; k <<= 1) {
            const bool up = ((t & k) == 0);
            #pragma unroll 1
            for (int j = k >> 1; j > 0; j >>= 1) {
                unsigned long long other;
                if (j >= 32) {
                    sbuf[p][t] = key;
                    __syncthreads();
                    other = sbuf[p][t ^ j];
                    p ^= 1;
                } else {
                    other = __shfl_xor_sync(0xFFFFFFFFu, key, j);
                }
                const bool lower = ((t & j) == 0);
                const bool keep_small = (up == lower);
                const bool take = keep_small ? (other < key) : (other > key);
                if (take) key = other;
            }
        }

        int perm = (int)(key & 0xFFFFFFFFu);
        int m = (perm < KMASK) ? 1 : 0;          // bool_mask at position t

        // Exclusive prefix sum of m (ballot + warp sums)
        const int lane = t & 31;
        const int warp = t >> 5;
        unsigned ballot = __ballot_sync(0xFFFFFFFFu, m);
        int before_in_warp = __popc(ballot & ((1u << lane) - 1u));
        if (lane == 0) warp_sums[warp] = __popc(ballot);
        __syncthreads();
        int warp_before = 0;
        #pragma unroll
        for (int w = 0; w < 32; ++w)
            warp_before += (w < warp) ? warp_sums[w] : 0;
        int t_before = warp_before + before_in_warp;

        float* masked_out = out + OFF_MIDX;
        float* unm_out    = out + OFF_UIDX;
        if (m) {
            masked_out[b * KMASK + t_before] = (float)t;
            g_info[b * NN + t] = -1;
        } else {
            int r = t - t_before;
            unm_out[b * NUNM + r] = (float)t;
            g_info[b * NN + t] = r;
        }

        // Publish: release g_info for this batch
        __syncthreads();
        if (t == 0) {
            __threadfence();
            atomicExch(&g_flag[b], 1);
        }
    } else {
        // ===================== CONSUMER: scatter 16 tokens =====================
        const int s    = blockIdx.x - BB;            // 0..2047
        const int b    = s / SCAT_PER_BATCH;
        const int tok0 = b * NN + (s % SCAT_PER_BATCH) * TOK_PER_BLK;

        // Preload mask_emb while waiting (independent of the flag)
        if (t < D4)
            s_me[t] = __ldg(reinterpret_cast<const float4*>(mask_emb) + t);

        if (t == 0) {
            while (atomicOr(&g_flag[b], 0) == 0) { __nanosleep(64); }
            __threadfence();                          // acquire
        }
        __syncthreads();

        if (t < TOK_PER_BLK) s_info[t] = g_info[tok0 + t];
        __syncthreads();

        float4* wm_base = reinterpret_cast<float4*>(out + OFF_WITHMASK);
        float4* be_base = reinterpret_cast<float4*>(out + OFF_BOOL);
        float4* up_base = reinterpret_cast<float4*>(out + OFF_UNMP);
        const float4* patch4 = reinterpret_cast<const float4*>(patch);

        const size_t blk_base = (size_t)tok0 * D4;   // sequential per block

        #pragma unroll
        for (int it = 0; it < (TOK_PER_BLK * D4) / 1024; ++it) {   // 3 iters
            const int idx = it * 1024 + t;            // 0..3071
            const int tl   = idx / D4;                // token within block
            const int lane = idx - tl * D4;           // float4 lane
            const int info = s_info[tl];
            const size_t g = blk_base + idx;

            const float bv = (info < 0) ? 1.0f : 0.0f;
            be_base[g] = make_float4(bv, bv, bv, bv);

            if (info < 0) {
                wm_base[g] = s_me[lane];
            } else {
                float4 pch = __ldg(patch4 + g);
                wm_base[g] = pch;
                up_base[((size_t)b * NUNM + info) * D4 + lane] = pch;
            }
        }

        // Restore flags for next graph replay: 64th consumer of batch resets.
        __syncthreads();
        if (t == 0) {
            int d = atomicAdd(&g_done[b], 1);
            if (d == SCAT_PER_BATCH - 1) {
                atomicExch(&g_done[b], 0);
                atomicExch(&g_flag[b], 0);
            }
        }
    }
}

extern "C" void kernel_launch(void* const* d_in, const int* in_sizes, int n_in,
                              void* d_out, int out_size)
{
    const float* patch    = (const float*)d_in[0];  // (B, N, D) f32
    const float* noise    = (const float*)d_in[1];  // (B, N)    f32
    const float* mask_emb = (const float*)d_in[2];  // (D,)      f32
    float* out = (float*)d_out;

    mask_fused_kernel<<<N_BLKS, 1024>>>(patch, noise, mask_emb, out);
}

// round 6
// speedup vs baseline: 1.3344x; 1.3344x over previous
#include <cuda_runtime.h>
#include <stdint.h>

// Problem constants
#define BB 32
#define NN 1024
#define DD 768
#define D4 (DD/4)          // 192 float4 per row
#define KMASK 768          // masked tokens per row
#define NUNM  256          // unmasked tokens per row

// Output layout (float32 concat of the 5 reference outputs, flattened in order)
#define OFF_WITHMASK 0ull
#define OFF_UNMP   ((unsigned long long)BB*NN*DD)                       // 25165824
#define OFF_BOOL   (OFF_UNMP + (unsigned long long)BB*NUNM*DD)          // 31457280
#define OFF_MIDX   (OFF_BOOL + (unsigned long long)BB*NN*DD)            // 56623104
#define OFF_UIDX   (OFF_MIDX + (unsigned long long)BB*KMASK)            // 56647680

// Scratch: per-token info. -1 => masked; else rank among unmasked (0..255)
__device__ int g_info[BB * NN];

// ---------------------------------------------------------------------------
// Kernel 1: hybrid register/shuffle bitonic argsort + fused finalize.
// One block of 1024 threads per batch row. Verified correct (R3/R4).
// Ends with cudaTriggerProgrammaticLaunchCompletion so the PDL-launched
// scatter can overlap its prologue with this kernel.
// ---------------------------------------------------------------------------
__global__ __launch_bounds__(1024, 1)
void mask_sort_kernel(const float* __restrict__ noise, float* __restrict__ out)
{
    __shared__ unsigned long long sbuf[2][NN];
    __shared__ int warp_sums[32];

    const int b = blockIdx.x;
    const int t = threadIdx.x;

    float v = noise[b * NN + t];
    unsigned long long key =
        ((unsigned long long)__float_as_uint(v) << 32) | (unsigned)t;

    int p = 0;
    #pragma unroll 1
    for (int k = 2; k <= NN; k <<= 1) {
        const bool up = ((t & k) == 0);
        #pragma unroll 1
        for (int j = k >> 1; j > 0; j >>= 1) {
            unsigned long long other;
            if (j >= 32) {
                sbuf[p][t] = key;
                __syncthreads();
                other = sbuf[p][t ^ j];
                p ^= 1;
            } else {
                other = __shfl_xor_sync(0xFFFFFFFFu, key, j);
            }
            const bool lower = ((t & j) == 0);
            const bool keep_small = (up == lower);
            const bool take = keep_small ? (other < key) : (other > key);
            if (take) key = other;
        }
    }

    // key now = t-th smallest; perm[t] = its original index
    int perm = (int)(key & 0xFFFFFFFFu);
    int m = (perm < KMASK) ? 1 : 0;   // bool_mask at position t

    // Exclusive prefix sum of m (ballot + warp sums)
    const int lane = t & 31;
    const int warp = t >> 5;
    unsigned ballot = __ballot_sync(0xFFFFFFFFu, m);
    int before_in_warp = __popc(ballot & ((1u << lane) - 1u));
    if (lane == 0) warp_sums[warp] = __popc(ballot);
    __syncthreads();
    int warp_before = 0;
    #pragma unroll
    for (int w = 0; w < 32; ++w)
        warp_before += (w < warp) ? warp_sums[w] : 0;
    int t_before = warp_before + before_in_warp;

    // order = stable argsort(bool_mask): False positions first, then True.
    float* masked_out = out + OFF_MIDX;
    float* unm_out    = out + OFF_UIDX;
    if (m) {
        masked_out[b * KMASK + t_before] = (float)t;
        g_info[b * NN + t] = -1;
    } else {
        int r = t - t_before;
        unm_out[b * NUNM + r] = (float)t;
        g_info[b * NN + t] = r;
    }

    // PDL: all prior stores become visible to the dependent grid after its
    // cudaGridDependencySynchronize once every block has triggered.
    cudaTriggerProgrammaticLaunchCompletion();
}

// ---------------------------------------------------------------------------
// Kernel 2: scatter, one token per block (32768 blocks x 192 thr, occ target
// 10 CTAs/SM = 1920 threads). PDL secondary: loads mask_emb BEFORE the grid
// dependency sync (independent of the sort), then syncs, then reads g_info.
// Streaming stores (__stcs) for all write-once outputs; __ldcs for the
// read-once patch rows.
// ---------------------------------------------------------------------------
__global__ __launch_bounds__(192, 10)
void mask_scatter_kernel(const float* __restrict__ patch,
                         const float* __restrict__ mask_emb,
                         float* __restrict__ out)
{
    const int tok = blockIdx.x;          // b*N + j
    const int b   = tok >> 10;
    const int t   = threadIdx.x;         // float4 lane 0..191

    // Independent of the sort result — overlap with producer via PDL.
    const float4 me = __ldg(reinterpret_cast<const float4*>(mask_emb) + t);

    cudaGridDependencySynchronize();

    const int info = __ldg(&g_info[tok]);

    float4* wm = reinterpret_cast<float4*>(out + OFF_WITHMASK) + (size_t)tok * D4;
    float4* be = reinterpret_cast<float4*>(out + OFF_BOOL)     + (size_t)tok * D4;

    const float bv = (info < 0) ? 1.0f : 0.0f;
    __stcs(be + t, make_float4(bv, bv, bv, bv));

    if (info < 0) {
        __stcs(wm + t, me);
    } else {
        float4 pch = __ldcs(reinterpret_cast<const float4*>(patch) + (size_t)tok * D4 + t);
        __stcs(wm + t, pch);
        float4* up = reinterpret_cast<float4*>(out + OFF_UNMP)
                   + ((size_t)b * NUNM + info) * D4;
        __stcs(up + t, pch);
    }
}

extern "C" void kernel_launch(void* const* d_in, const int* in_sizes, int n_in,
                              void* d_out, int out_size)
{
    const float* patch    = (const float*)d_in[0];  // (B, N, D) f32
    const float* noise    = (const float*)d_in[1];  // (B, N)    f32
    const float* mask_emb = (const float*)d_in[2];  // (D,)      f32
    float* out = (float*)d_out;

    // Primary
    mask_sort_kernel<<<BB, 1024>>>(noise, out);

    // Secondary with programmatic dependent launch (overlaps prologue with primary)
    cudaLaunchAttribute attrs[1];
    attrs[0].id = cudaLaunchAttributeProgrammaticStreamSerialization;
    attrs[0].val.programmaticStreamSerializationAllowed = 1;

    cudaLaunchConfig_t cfg = {};
    cfg.gridDim  = dim3(BB * NN, 1, 1);
    cfg.blockDim = dim3(192, 1, 1);
    cfg.dynamicSmemBytes = 0;
    cfg.stream = 0;
    cfg.attrs = attrs;
    cfg.numAttrs = 1;

    cudaLaunchKernelEx(&cfg, mask_scatter_kernel, patch, mask_emb, out);
}